// round 2
// baseline (speedup 1.0000x reference)
#include <cuda_runtime.h>
#include <cuda_bf16.h>
#include <cstdint>

// Problem constants
#define B_    2
#define S_    4096
#define D_    1024
#define H_    16
#define DH_   64
#define NFULL 7          // full windows of 1024, stride 512
#define ROWS_OUT 7680    // per-batch output rows: 7*1024 + 512
#define SCALE 0.125f     // 1/sqrt(64)

// Scratch (allocation-free: device globals)
__device__ float g_qkv[B_ * S_ * 3 * D_];       // [B*S, 3072] per-token QKV
__device__ float g_o  [B_ * ROWS_OUT * D_];     // attention output rows

// ---------------------------------------------------------------------------
// helpers
// ---------------------------------------------------------------------------
__device__ __forceinline__ uint32_t f2tf(float x) {
    uint32_t y;
    asm("cvt.rna.tf32.f32 %0, %1;" : "=r"(y) : "f"(x));
    return y;
}

__device__ __forceinline__ void mma_tf32(float* c, const uint32_t* a, const uint32_t* b) {
    asm volatile(
        "mma.sync.aligned.m16n8k8.row.col.f32.tf32.tf32.f32 "
        "{%0,%1,%2,%3}, {%4,%5,%6,%7}, {%8,%9}, {%0,%1,%2,%3};"
        : "+f"(c[0]), "+f"(c[1]), "+f"(c[2]), "+f"(c[3])
        : "r"(a[0]), "r"(a[1]), "r"(a[2]), "r"(a[3]),
          "r"(b[0]), "r"(b[1]));
}

__device__ __forceinline__ void cp16(float* s, const float* g) {
    uint32_t sa = (uint32_t)__cvta_generic_to_shared(s);
    asm volatile("cp.async.cg.shared.global [%0], [%1], 16;" :: "r"(sa), "l"(g));
}

// ---------------------------------------------------------------------------
// GEMM: C[M,N] = A[M,K] @ B[N,K]^T + bias[N]
// A row-major (K contiguous), Bw row-major [N,K] (i.e. already "col" layout for
// mma row.col). M%128==0, N%128==0, K%32==0 for all call sites here.
// 256 threads, 128x128x32 tiles, cp.async double buffer.
// Dynamic smem: 4 * 128 * 36 * 4 = 73728 bytes.
// ---------------------------------------------------------------------------
__global__ void gemm_tf32_kernel(const float* __restrict__ A,
                                 const float* __restrict__ Bw,
                                 const float* __restrict__ bias,
                                 float* __restrict__ C,
                                 int M, int N, int K)
{
    extern __shared__ float smg[];
    const int SMS = 128 * 36;
    float* As = smg;           // [2][128][36]
    float* Bs = smg + 2 * SMS; // [2][128][36]

    const int tid  = threadIdx.x;
    const int lane = tid & 31;
    const int warp = tid >> 5;
    const int wm = warp >> 2;   // 0..1 -> 64-row strip
    const int wn = warp & 3;    // 0..3 -> 32-col strip
    const int bm = blockIdx.y * 128;
    const int bn = blockIdx.x * 128;

    float acc[4][4][4];
#pragma unroll
    for (int i = 0; i < 4; i++)
#pragma unroll
        for (int j = 0; j < 4; j++)
#pragma unroll
            for (int t = 0; t < 4; t++) acc[i][j][t] = 0.f;

    auto loadTile = [&](int buf, int k0) {
#pragma unroll
        for (int i = 0; i < 4; i++) {
            int lin = i * 256 + tid;
            int row = lin >> 3;            // 8 float4 per row of 32
            int c4  = (lin & 7) << 2;
            cp16(&As[buf * SMS + row * 36 + c4], &A[(bm + row) * K + k0 + c4]);
            cp16(&Bs[buf * SMS + row * 36 + c4], &Bw[(bn + row) * K + k0 + c4]);
        }
    };

    loadTile(0, 0);
    asm volatile("cp.async.commit_group;");

    const int nk = K >> 5;
    for (int kt = 0; kt < nk; kt++) {
        const int buf = kt & 1;
        if (kt + 1 < nk) {
            loadTile(buf ^ 1, (kt + 1) << 5);
            asm volatile("cp.async.commit_group;");
            asm volatile("cp.async.wait_group 1;");
        } else {
            asm volatile("cp.async.wait_group 0;");
        }
        __syncthreads();

        const float* Ab = &As[buf * SMS];
        const float* Bb = &Bs[buf * SMS];
#pragma unroll
        for (int kk = 0; kk < 4; kk++) {
            const int kb = kk * 8;
            uint32_t af[4][4], bf[4][2];
#pragma unroll
            for (int mi = 0; mi < 4; mi++) {
                int r = wm * 64 + mi * 16 + (lane >> 2);
                int c = kb + (lane & 3);
                af[mi][0] = f2tf(Ab[r * 36 + c]);
                af[mi][1] = f2tf(Ab[(r + 8) * 36 + c]);
                af[mi][2] = f2tf(Ab[r * 36 + c + 4]);
                af[mi][3] = f2tf(Ab[(r + 8) * 36 + c + 4]);
            }
#pragma unroll
            for (int ni = 0; ni < 4; ni++) {
                int r = wn * 32 + ni * 8 + (lane >> 2);
                bf[ni][0] = f2tf(Bb[r * 36 + kb + (lane & 3)]);
                bf[ni][1] = f2tf(Bb[r * 36 + kb + (lane & 3) + 4]);
            }
#pragma unroll
            for (int mi = 0; mi < 4; mi++)
#pragma unroll
                for (int ni = 0; ni < 4; ni++)
                    mma_tf32(acc[mi][ni], af[mi], bf[ni]);
        }
        __syncthreads();
    }

    // epilogue: C = acc + bias
#pragma unroll
    for (int mi = 0; mi < 4; mi++) {
#pragma unroll
        for (int ni = 0; ni < 4; ni++) {
            int r = bm + wm * 64 + mi * 16 + (lane >> 2);
            int c = bn + wn * 32 + ni * 8 + ((lane & 3) << 1);
            float b0 = bias[c], b1 = bias[c + 1];
            C[r * N + c]           = acc[mi][ni][0] + b0;
            C[r * N + c + 1]       = acc[mi][ni][1] + b1;
            C[(r + 8) * N + c]     = acc[mi][ni][2] + b0;
            C[(r + 8) * N + c + 1] = acc[mi][ni][3] + b1;
        }
    }
}

// ---------------------------------------------------------------------------
// Flash attention over a window. One block = 64 Q rows of one (batch, window,
// head). 4 warps x 16 rows. K/V staged in 64-row tiles; online softmax in the
// m16n8 C-fragment layout; P goes through per-warp SMEM (reusing the Q staging
// buffer) to form the A fragment of P@V.
// Dynamic smem: 3 * 64 * 72 * 4 = 55296 bytes.
// ---------------------------------------------------------------------------
__global__ void attn_kernel(const float* __restrict__ qkv, float* __restrict__ o)
{
    extern __shared__ float sm[];
    float* Ks = sm;               // [64][72]
    float* Vs = sm + 64 * 72;     // [64][72]
    float* Qs = sm + 2 * 64 * 72; // [64][72], later reused as P

    const int tid  = threadIdx.x;
    const int lane = tid & 31;
    const int warp = tid >> 5;

    const int FULLC = B_ * NFULL * H_ * 16;
    int idx = blockIdx.x;
    int b, h, qt, xrow0, orow0, L;
    if (idx < FULLC) {
        b = idx / (NFULL * H_ * 16);
        int r  = idx % (NFULL * H_ * 16);
        int win = r / (H_ * 16);
        int r2  = r % (H_ * 16);
        h  = r2 >> 4;
        qt = r2 & 15;
        L = 1024;
        xrow0 = b * S_ + win * 512;
        orow0 = b * ROWS_OUT + win * 1024 + qt * 64;
    } else {
        int j = idx - FULLC;
        b = j / (H_ * 8);
        int r2 = j % (H_ * 8);
        h  = r2 >> 3;
        qt = r2 & 7;
        L = 512;
        xrow0 = b * S_ + 3584;
        orow0 = b * ROWS_OUT + 7168 + qt * 64;
    }
    const int qbase = xrow0 + qt * 64;

    // stage scaled Q tile [64][64] into Qs (scale = 1/8, exact power of two)
    for (int i = tid; i < 64 * 16; i += 128) {
        int r  = i >> 4;
        int c4 = (i & 15) << 2;
        float4 v = *reinterpret_cast<const float4*>(
            &qkv[(qbase + r) * 3072 + h * 64 + c4]);
        v.x *= SCALE; v.y *= SCALE; v.z *= SCALE; v.w *= SCALE;
        *reinterpret_cast<float4*>(&Qs[r * 72 + c4]) = v;
    }
    __syncthreads();

    // Q fragments: A-frag for 8 k-steps of 8 (DH=64), held in registers
    uint32_t qf[8][4];
    {
        int r0 = warp * 16 + (lane >> 2);
#pragma unroll
        for (int kk = 0; kk < 8; kk++) {
            int c = kk * 8 + (lane & 3);
            qf[kk][0] = f2tf(Qs[r0 * 72 + c]);
            qf[kk][1] = f2tf(Qs[(r0 + 8) * 72 + c]);
            qf[kk][2] = f2tf(Qs[r0 * 72 + c + 4]);
            qf[kk][3] = f2tf(Qs[(r0 + 8) * 72 + c + 4]);
        }
    }

    float oacc[8][4];
#pragma unroll
    for (int i = 0; i < 8; i++)
#pragma unroll
        for (int t = 0; t < 4; t++) oacc[i][t] = 0.f;
    float m0 = -1e30f, m1 = -1e30f, l0 = 0.f, l1 = 0.f;

    const int pr = lane >> 2;
    float* Ps = Qs + warp * 16 * 72;   // per-warp 16-row P buffer (Q staging is dead)

    const int ntiles = L >> 6;
    for (int nt = 0; nt < ntiles; nt++) {
        __syncthreads();   // prior-tile Ks/Vs reads complete; Q-frag reads complete
        const int kvrow0 = xrow0 + nt * 64;
        for (int i = tid; i < 64 * 16; i += 128) {
            int r  = i >> 4;
            int c4 = (i & 15) << 2;
            *reinterpret_cast<float4*>(&Ks[r * 72 + c4]) =
                *reinterpret_cast<const float4*>(
                    &qkv[(kvrow0 + r) * 3072 + 1024 + h * 64 + c4]);
            *reinterpret_cast<float4*>(&Vs[r * 72 + c4]) =
                *reinterpret_cast<const float4*>(
                    &qkv[(kvrow0 + r) * 3072 + 2048 + h * 64 + c4]);
        }
        __syncthreads();

        // S = Q @ K^T  (16 q-rows x 64 kv-cols per warp)
        float sacc[8][4];
#pragma unroll
        for (int i = 0; i < 8; i++)
#pragma unroll
            for (int t = 0; t < 4; t++) sacc[i][t] = 0.f;
#pragma unroll
        for (int kk = 0; kk < 8; kk++) {
            uint32_t bf[8][2];
#pragma unroll
            for (int ni = 0; ni < 8; ni++) {
                int r = ni * 8 + (lane >> 2);
                bf[ni][0] = f2tf(Ks[r * 72 + kk * 8 + (lane & 3)]);
                bf[ni][1] = f2tf(Ks[r * 72 + kk * 8 + (lane & 3) + 4]);
            }
#pragma unroll
            for (int ni = 0; ni < 8; ni++) mma_tf32(sacc[ni], qf[kk], bf[ni]);
        }

        // online softmax (rows pr and pr+8 of warp tile)
        float tm0 = -1e30f, tm1 = -1e30f;
#pragma unroll
        for (int ni = 0; ni < 8; ni++) {
            tm0 = fmaxf(tm0, fmaxf(sacc[ni][0], sacc[ni][1]));
            tm1 = fmaxf(tm1, fmaxf(sacc[ni][2], sacc[ni][3]));
        }
        tm0 = fmaxf(tm0, __shfl_xor_sync(0xffffffffu, tm0, 1));
        tm0 = fmaxf(tm0, __shfl_xor_sync(0xffffffffu, tm0, 2));
        tm1 = fmaxf(tm1, __shfl_xor_sync(0xffffffffu, tm1, 1));
        tm1 = fmaxf(tm1, __shfl_xor_sync(0xffffffffu, tm1, 2));
        float mn0 = fmaxf(m0, tm0), mn1 = fmaxf(m1, tm1);
        float c0 = __expf(m0 - mn0), c1 = __expf(m1 - mn1);
        m0 = mn0; m1 = mn1;

        float rs0 = 0.f, rs1 = 0.f;
#pragma unroll
        for (int ni = 0; ni < 8; ni++) {
            float p0 = __expf(sacc[ni][0] - m0);
            float p1 = __expf(sacc[ni][1] - m0);
            float p2 = __expf(sacc[ni][2] - m1);
            float p3 = __expf(sacc[ni][3] - m1);
            rs0 += p0 + p1;
            rs1 += p2 + p3;
            int c = ni * 8 + ((lane & 3) << 1);
            Ps[pr * 72 + c]           = p0;
            Ps[pr * 72 + c + 1]       = p1;
            Ps[(pr + 8) * 72 + c]     = p2;
            Ps[(pr + 8) * 72 + c + 1] = p3;
        }
        rs0 += __shfl_xor_sync(0xffffffffu, rs0, 1);
        rs0 += __shfl_xor_sync(0xffffffffu, rs0, 2);
        rs1 += __shfl_xor_sync(0xffffffffu, rs1, 1);
        rs1 += __shfl_xor_sync(0xffffffffu, rs1, 2);
        l0 = l0 * c0 + rs0;
        l1 = l1 * c1 + rs1;
#pragma unroll
        for (int ni = 0; ni < 8; ni++) {
            oacc[ni][0] *= c0; oacc[ni][1] *= c0;
            oacc[ni][2] *= c1; oacc[ni][3] *= c1;
        }
        __syncwarp();   // Ps writes -> cross-lane Ps reads (warp-private buffer)

        // O += P @ V
#pragma unroll
        for (int kk = 0; kk < 8; kk++) {
            uint32_t ap[4];
            int c = kk * 8 + (lane & 3);
            ap[0] = f2tf(Ps[pr * 72 + c]);
            ap[1] = f2tf(Ps[(pr + 8) * 72 + c]);
            ap[2] = f2tf(Ps[pr * 72 + c + 4]);
            ap[3] = f2tf(Ps[(pr + 8) * 72 + c + 4]);
#pragma unroll
            for (int ni = 0; ni < 8; ni++) {
                uint32_t bv[2];
                bv[0] = f2tf(Vs[(kk * 8 + (lane & 3)) * 72 + ni * 8 + (lane >> 2)]);
                bv[1] = f2tf(Vs[(kk * 8 + (lane & 3) + 4) * 72 + ni * 8 + (lane >> 2)]);
                mma_tf32(oacc[ni], ap, bv);
            }
        }
    }

    // epilogue: O / l
    const float inv0 = 1.f / l0, inv1 = 1.f / l1;
    const int r0g = orow0 + warp * 16 + pr;
#pragma unroll
    for (int ni = 0; ni < 8; ni++) {
        int c = h * 64 + ni * 8 + ((lane & 3) << 1);
        o[r0g * D_ + c]             = oacc[ni][0] * inv0;
        o[r0g * D_ + c + 1]         = oacc[ni][1] * inv0;
        o[(r0g + 8) * D_ + c]       = oacc[ni][2] * inv1;
        o[(r0g + 8) * D_ + c + 1]   = oacc[ni][3] * inv1;
    }
}

// ---------------------------------------------------------------------------
// launch
// ---------------------------------------------------------------------------
extern "C" void kernel_launch(void* const* d_in, const int* in_sizes, int n_in,
                              void* d_out, int out_size)
{
    (void)in_sizes; (void)n_in; (void)out_size;
    const float* x     = (const float*)d_in[0];
    const float* W_in  = (const float*)d_in[1];
    const float* b_in  = (const float*)d_in[2];
    const float* W_out = (const float*)d_in[3];
    const float* b_out = (const float*)d_in[4];
    float* out = (float*)d_out;

    float* qkv = nullptr;
    float* ob  = nullptr;
    cudaGetSymbolAddress((void**)&qkv, g_qkv);
    cudaGetSymbolAddress((void**)&ob,  g_o);

    // >48KB dynamic smem requires the attribute; harness calls kernel_launch
    // before capture, so this is already set by capture time (idempotent).
    cudaFuncSetAttribute(gemm_tf32_kernel,
                         cudaFuncAttributeMaxDynamicSharedMemorySize, 73728);
    cudaFuncSetAttribute(attn_kernel,
                         cudaFuncAttributeMaxDynamicSharedMemorySize, 55296);

    // 1) per-token QKV: [8192,1024] @ [1024,3072] + b_in
    dim3 g1(3072 / 128, 8192 / 128);
    gemm_tf32_kernel<<<g1, 256, 73728>>>(x, W_in, b_in, qkv,
                                         B_ * S_, 3 * D_, D_);

    // 2) windowed flash attention: 2*7*16*16 full tiles + 2*16*8 partial
    const int nblk = B_ * NFULL * H_ * 16 + B_ * H_ * 8;  // 3840
    attn_kernel<<<nblk, 128, 55296>>>(qkv, ob);

    // 3) output projection: [15360,1024] @ [1024,1024] + b_out
    dim3 g3(1024 / 128, (B_ * ROWS_OUT) / 128);
    gemm_tf32_kernel<<<g3, 256, 73728>>>(ob, W_out, b_out, out,
                                         B_ * ROWS_OUT, D_, D_);
}

// round 4
// speedup vs baseline: 2.3654x; 2.3654x over previous
#include <cuda_runtime.h>
#include <cuda_fp16.h>
#include <cstdint>

// Problem constants
#define B_    2
#define S_    4096
#define D_    1024
#define H_    16
#define NFULL 7          // full windows of 1024, stride 512
#define ROWS_OUT 7680    // per-batch output rows: 7*1024 + 512
#define SCALE 0.125f     // 1/sqrt(64)

// Scratch (allocation-free device globals), all fp16
__device__ __align__(16) __half g_xh  [B_ * S_ * D_];          // x in half
__device__ __align__(16) __half g_wih [3 * D_ * D_];           // W_in in half
__device__ __align__(16) __half g_woh [D_ * D_];               // W_out in half
__device__ __align__(16) __half g_qkvh[B_ * S_ * 3 * D_];      // per-token QKV (half)
__device__ __align__(16) __half g_oh  [B_ * ROWS_OUT * D_];    // attention out (half)

// ---------------------------------------------------------------------------
// helpers
// ---------------------------------------------------------------------------
__device__ __forceinline__ uint32_t smem_u32(const void* p) {
    uint32_t a;
    asm("{ .reg .u64 t; cvta.to.shared.u64 t, %1; cvt.u32.u64 %0, t; }"
        : "=r"(a) : "l"(p));
    return a;
}

__device__ __forceinline__ void cp16(void* s, const void* g) {
    uint32_t sa = (uint32_t)__cvta_generic_to_shared(s);
    asm volatile("cp.async.cg.shared.global [%0], [%1], 16;" :: "r"(sa), "l"(g));
}

__device__ __forceinline__ void ldsm_x4(uint32_t* r, uint32_t addr) {
    asm volatile("ldmatrix.sync.aligned.m8n8.x4.shared.b16 {%0,%1,%2,%3}, [%4];"
                 : "=r"(r[0]), "=r"(r[1]), "=r"(r[2]), "=r"(r[3]) : "r"(addr));
}

__device__ __forceinline__ void ldsm_x4_t(uint32_t* r, uint32_t addr) {
    asm volatile("ldmatrix.sync.aligned.m8n8.x4.trans.shared.b16 {%0,%1,%2,%3}, [%4];"
                 : "=r"(r[0]), "=r"(r[1]), "=r"(r[2]), "=r"(r[3]) : "r"(addr));
}

// D(f32) += A(f16,row) @ B(f16,col): m16n8k16
__device__ __forceinline__ void mma_f16(float* c, const uint32_t* a, const uint32_t* b) {
    asm volatile(
        "mma.sync.aligned.m16n8k16.row.col.f32.f16.f16.f32 "
        "{%0,%1,%2,%3}, {%4,%5,%6,%7}, {%8,%9}, {%0,%1,%2,%3};"
        : "+f"(c[0]), "+f"(c[1]), "+f"(c[2]), "+f"(c[3])
        : "r"(a[0]), "r"(a[1]), "r"(a[2]), "r"(a[3]),
          "r"(b[0]), "r"(b[1]));
}

// ---------------------------------------------------------------------------
// f32 -> f16 conversion (vectorized, grid-stride)
// ---------------------------------------------------------------------------
__global__ void cvt_f16_kernel(const float4* __restrict__ in,
                               __half2* __restrict__ out, int n4)
{
    for (int i = blockIdx.x * blockDim.x + threadIdx.x; i < n4;
         i += gridDim.x * blockDim.x) {
        float4 v = in[i];
        out[2 * i]     = __floats2half2_rn(v.x, v.y);
        out[2 * i + 1] = __floats2half2_rn(v.z, v.w);
    }
}

// ---------------------------------------------------------------------------
// fp16 GEMM: C[M,N] = Ah[M,K] @ Bh[N,K]^T + bias[N]
// Ah row-major (K contiguous), Bh row-major [N,K] = the "col" operand.
// CTA 128x128, K chunk 64 (4 x k16), 256 threads, cp.async double buffer,
// all fragments via ldmatrix. Requires M%128==0, N%128==0, K%64==0.
// Dynamic smem: 2 buffers * (A 128x72h + B 128x72h) = 73728 bytes.
// OUT_HALF: write __half C, else float C.
// ---------------------------------------------------------------------------
template <bool OUT_HALF>
__global__ __launch_bounds__(256) void gemm_f16_kernel(
    const __half* __restrict__ A, const __half* __restrict__ Bw,
    const float* __restrict__ bias, void* __restrict__ Cv,
    int M, int N, int K)
{
    extern __shared__ char smg[];
    const uint32_t smb = smem_u32(smg);
    const int tid  = threadIdx.x;
    const int lane = tid & 31;
    const int warp = tid >> 5;
    const int wm = warp >> 2;   // 0..1 -> 64-row strip
    const int wn = warp & 3;    // 0..3 -> 32-col strip
    const int bm = blockIdx.y * 128;
    const int bn = blockIdx.x * 128;

    // buffer b: A at b*36864, B at b*36864+18432; row stride 144B (72 halfs)
    auto stage = [&](int kt, int b) {
        const __half* Ag = A  + (size_t)bm * K + kt * 64;
        const __half* Bg = Bw + (size_t)bn * K + kt * 64;
        char* Ab = smg + b * 36864;
        char* Bb = Ab + 18432;
#pragma unroll
        for (int i = 0; i < 4; i++) {
            int lin = i * 256 + tid;
            int row = lin >> 3;          // 0..127
            int j   = lin & 7;           // 16B segment in row
            cp16(Ab + row * 144 + j * 16, Ag + (size_t)row * K + j * 8);
            cp16(Bb + row * 144 + j * 16, Bg + (size_t)row * K + j * 8);
        }
    };

    float acc[4][4][4];
#pragma unroll
    for (int i = 0; i < 4; i++)
#pragma unroll
        for (int j = 0; j < 4; j++)
#pragma unroll
            for (int t = 0; t < 4; t++) acc[i][j][t] = 0.f;

    stage(0, 0);
    asm volatile("cp.async.commit_group;");

    const int nk = K >> 6;
    // fragment address components (constant per thread)
    const int arow = (lane & 7) + ((lane >> 3) & 1) * 8;  // A: row-in-16 quad
    const int acol = (lane >> 4) * 8;                     // A: col quad
    const int brow = (lane & 7) + ((lane >> 4) << 3);     // B: n-row quad
    const int bcol = ((lane >> 3) & 1) * 8;               // B: k quad

    for (int kt = 0; kt < nk; kt++) {
        const int b = kt & 1;
        if (kt + 1 < nk) {
            stage(kt + 1, b ^ 1);
            asm volatile("cp.async.commit_group;");
            asm volatile("cp.async.wait_group 1;");
        } else {
            asm volatile("cp.async.wait_group 0;");
        }
        __syncthreads();

        const uint32_t Abase = smb + b * 36864;
        const uint32_t Bbase = Abase + 18432;
#pragma unroll
        for (int kk = 0; kk < 4; kk++) {
            const int kb = kk * 16;
            uint32_t a[4][4], bb[2][4];
#pragma unroll
            for (int mi = 0; mi < 4; mi++)
                ldsm_x4(a[mi], Abase + (wm * 64 + mi * 16 + arow) * 144
                               + (kb + acol) * 2);
#pragma unroll
            for (int nj = 0; nj < 2; nj++)
                ldsm_x4(bb[nj], Bbase + (wn * 32 + nj * 16 + brow) * 144
                                + (kb + bcol) * 2);
#pragma unroll
            for (int mi = 0; mi < 4; mi++)
#pragma unroll
                for (int ni = 0; ni < 4; ni++)
                    mma_f16(acc[mi][ni], a[mi], &bb[ni >> 1][(ni & 1) * 2]);
        }
        __syncthreads();
    }

    // epilogue
#pragma unroll
    for (int mi = 0; mi < 4; mi++) {
#pragma unroll
        for (int ni = 0; ni < 4; ni++) {
            int r = bm + wm * 64 + mi * 16 + (lane >> 2);
            int c = bn + wn * 32 + ni * 8 + ((lane & 3) << 1);
            float b0 = bias[c], b1 = bias[c + 1];
            if (OUT_HALF) {
                __half* C = (__half*)Cv;
                *reinterpret_cast<__half2*>(&C[(size_t)r * N + c]) =
                    __floats2half2_rn(acc[mi][ni][0] + b0, acc[mi][ni][1] + b1);
                *reinterpret_cast<__half2*>(&C[(size_t)(r + 8) * N + c]) =
                    __floats2half2_rn(acc[mi][ni][2] + b0, acc[mi][ni][3] + b1);
            } else {
                float* C = (float*)Cv;
                C[(size_t)r * N + c]           = acc[mi][ni][0] + b0;
                C[(size_t)r * N + c + 1]       = acc[mi][ni][1] + b1;
                C[(size_t)(r + 8) * N + c]     = acc[mi][ni][2] + b0;
                C[(size_t)(r + 8) * N + c + 1] = acc[mi][ni][3] + b1;
            }
        }
    }
}

// ---------------------------------------------------------------------------
// fp16 flash attention over a window. One block = 64 Q rows of one
// (batch, window, head). 4 warps x 16 rows. K/V double-buffered via cp.async.
// All MMA fragments via ldmatrix (V transposed by ldmatrix.trans).
// SMEM (bytes): K0 V0 K1 V1 Q = 5 * 64*72*2 = 46080.
// ---------------------------------------------------------------------------
__global__ __launch_bounds__(128) void attn_kernel(
    const __half* __restrict__ qkv, __half* __restrict__ o)
{
    extern __shared__ char sma[];
    const uint32_t smb = smem_u32(sma);
    __half* Qh = reinterpret_cast<__half*>(sma + 36864);

    const int tid  = threadIdx.x;
    const int lane = tid & 31;
    const int warp = tid >> 5;

    const int FULLC = B_ * NFULL * H_ * 16;
    int idx = blockIdx.x;
    int b, h, qt, xrow0, orow0, L;
    if (idx < FULLC) {
        b = idx / (NFULL * H_ * 16);
        int r  = idx % (NFULL * H_ * 16);
        int win = r / (H_ * 16);
        int r2  = r % (H_ * 16);
        h  = r2 >> 4;
        qt = r2 & 15;
        L = 1024;
        xrow0 = b * S_ + win * 512;
        orow0 = b * ROWS_OUT + win * 1024 + qt * 64;
    } else {
        int j = idx - FULLC;
        b = j / (H_ * 8);
        int r2 = j % (H_ * 8);
        h  = r2 >> 3;
        qt = r2 & 7;
        L = 512;
        xrow0 = b * S_ + 3584;
        orow0 = b * ROWS_OUT + 7168 + qt * 64;
    }
    const int qbase = xrow0 + qt * 64;

    // stage K/V tile nt into buffer bb (cp.async)
    auto stage_kv = [&](int nt, int bb) {
        const int kvrow0 = xrow0 + nt * 64;
        char* Kb = sma + bb * 18432;
        char* Vb = Kb + 9216;
#pragma unroll
        for (int i = 0; i < 4; i++) {
            int lin = i * 128 + tid;
            int row = lin >> 3;
            int j   = lin & 7;
            const __half* base = qkv + (size_t)(kvrow0 + row) * 3072 + h * 64 + j * 8;
            cp16(Kb + row * 144 + j * 16, base + 1024);
            cp16(Vb + row * 144 + j * 16, base + 2048);
        }
    };

    stage_kv(0, 0);
    asm volatile("cp.async.commit_group;");

    // stage scaled Q (regular ld/st, *1/8 exact in half)
    const __half2 s2 = __float2half2_rn(SCALE);
#pragma unroll
    for (int i = 0; i < 4; i++) {
        int lin = i * 128 + tid;
        int row = lin >> 3;
        int j   = lin & 7;
        uint4 v = *reinterpret_cast<const uint4*>(
            qkv + (size_t)(qbase + row) * 3072 + h * 64 + j * 8);
        __half2* hv = reinterpret_cast<__half2*>(&v);
        hv[0] = __hmul2(hv[0], s2);
        hv[1] = __hmul2(hv[1], s2);
        hv[2] = __hmul2(hv[2], s2);
        hv[3] = __hmul2(hv[3], s2);
        *reinterpret_cast<uint4*>(&Qh[row * 72 + j * 8]) = v;
    }
    __syncthreads();

    // quad components for ldmatrix addressing
    const int arow = (lane & 7) + ((lane >> 3) & 1) * 8;   // A-type (row quad)
    const int acol = (lane >> 4) * 8;
    const int brow = (lane & 7) + ((lane >> 4) << 3);      // B-type (n quad)
    const int bcol = ((lane >> 3) & 1) * 8;

    // Q fragments: 4 kk steps of k16
    const uint32_t Qbase = smb + 36864;
    uint32_t qf[4][4];
#pragma unroll
    for (int kk = 0; kk < 4; kk++)
        ldsm_x4(qf[kk], Qbase + (warp * 16 + arow) * 144 + (kk * 16 + acol) * 2);
    __syncthreads();   // Q frags in regs before Qh is reused as P

    float oacc[8][4];
#pragma unroll
    for (int i = 0; i < 8; i++)
#pragma unroll
        for (int t = 0; t < 4; t++) oacc[i][t] = 0.f;
    float m0 = -1e30f, m1 = -1e30f, l0 = 0.f, l1 = 0.f;

    const int pr = lane >> 2;
    // per-warp 16-row P buffer inside the (dead) Q staging area
    __half* Ps = Qh + warp * 16 * 72;
    const uint32_t Pbase = Qbase + warp * 16 * 144;

    const int ntiles = L >> 6;
    for (int nt = 0; nt < ntiles; nt++) {
        const int bb = nt & 1;
        if (nt + 1 < ntiles) {
            stage_kv(nt + 1, bb ^ 1);
            asm volatile("cp.async.commit_group;");
            asm volatile("cp.async.wait_group 1;");
        } else {
            asm volatile("cp.async.wait_group 0;");
        }
        __syncthreads();

        const uint32_t Kbase = smb + bb * 18432;
        const uint32_t Vbase = Kbase + 9216;

        // S = Q @ K^T (16 q-rows x 64 kv per warp)
        float sacc[8][4];
#pragma unroll
        for (int i = 0; i < 8; i++)
#pragma unroll
            for (int t = 0; t < 4; t++) sacc[i][t] = 0.f;
#pragma unroll
        for (int kk = 0; kk < 4; kk++) {
            uint32_t kf[4][4];
#pragma unroll
            for (int nB = 0; nB < 4; nB++)
                ldsm_x4(kf[nB], Kbase + (nB * 16 + brow) * 144
                               + (kk * 16 + bcol) * 2);
#pragma unroll
            for (int ni = 0; ni < 8; ni++)
                mma_f16(sacc[ni], qf[kk], &kf[ni >> 1][(ni & 1) * 2]);
        }

        // online softmax (rows pr, pr+8)
        float tm0 = -1e30f, tm1 = -1e30f;
#pragma unroll
        for (int ni = 0; ni < 8; ni++) {
            tm0 = fmaxf(tm0, fmaxf(sacc[ni][0], sacc[ni][1]));
            tm1 = fmaxf(tm1, fmaxf(sacc[ni][2], sacc[ni][3]));
        }
        tm0 = fmaxf(tm0, __shfl_xor_sync(0xffffffffu, tm0, 1));
        tm0 = fmaxf(tm0, __shfl_xor_sync(0xffffffffu, tm0, 2));
        tm1 = fmaxf(tm1, __shfl_xor_sync(0xffffffffu, tm1, 1));
        tm1 = fmaxf(tm1, __shfl_xor_sync(0xffffffffu, tm1, 2));
        float mn0 = fmaxf(m0, tm0), mn1 = fmaxf(m1, tm1);
        float c0 = __expf(m0 - mn0), c1 = __expf(m1 - mn1);
        m0 = mn0; m1 = mn1;

        float rs0 = 0.f, rs1 = 0.f;
#pragma unroll
        for (int ni = 0; ni < 8; ni++) {
            float p0 = __expf(sacc[ni][0] - m0);
            float p1 = __expf(sacc[ni][1] - m0);
            float p2 = __expf(sacc[ni][2] - m1);
            float p3 = __expf(sacc[ni][3] - m1);
            rs0 += p0 + p1;
            rs1 += p2 + p3;
            int c = ni * 8 + ((lane & 3) << 1);
            *reinterpret_cast<__half2*>(&Ps[pr * 72 + c])       = __floats2half2_rn(p0, p1);
            *reinterpret_cast<__half2*>(&Ps[(pr + 8) * 72 + c]) = __floats2half2_rn(p2, p3);
        }
        rs0 += __shfl_xor_sync(0xffffffffu, rs0, 1);
        rs0 += __shfl_xor_sync(0xffffffffu, rs0, 2);
        rs1 += __shfl_xor_sync(0xffffffffu, rs1, 1);
        rs1 += __shfl_xor_sync(0xffffffffu, rs1, 2);
        l0 = l0 * c0 + rs0;
        l1 = l1 * c1 + rs1;
#pragma unroll
        for (int ni = 0; ni < 8; ni++) {
            oacc[ni][0] *= c0; oacc[ni][1] *= c0;
            oacc[ni][2] *= c1; oacc[ni][3] *= c1;
        }
        __syncwarp();   // Ps writes -> cross-lane ldmatrix reads (warp-private)

        // O += P @ V  (V fragments via ldmatrix.trans)
#pragma unroll
        for (int kk = 0; kk < 4; kk++) {
            uint32_t pf[4], vf[4][4];
            ldsm_x4(pf, Pbase + arow * 144 + (kk * 16 + acol) * 2);
#pragma unroll
            for (int nB = 0; nB < 4; nB++)
                ldsm_x4_t(vf[nB], Vbase + (kk * 16 + (((lane >> 3) & 1) << 3)
                                           + (lane & 7)) * 144
                                 + (nB * 16 + ((lane >> 4) << 3)) * 2);
#pragma unroll
            for (int ni = 0; ni < 8; ni++)
                mma_f16(oacc[ni], pf, &vf[ni >> 1][(ni & 1) * 2]);
        }
        __syncthreads();   // done reading this KV buffer before next overwrite
    }

    // epilogue: O / l  -> half
    const float inv0 = 1.f / l0, inv1 = 1.f / l1;
    const int r0g = orow0 + warp * 16 + pr;
#pragma unroll
    for (int ni = 0; ni < 8; ni++) {
        int c = h * 64 + ni * 8 + ((lane & 3) << 1);
        *reinterpret_cast<__half2*>(&o[(size_t)r0g * D_ + c]) =
            __floats2half2_rn(oacc[ni][0] * inv0, oacc[ni][1] * inv0);
        *reinterpret_cast<__half2*>(&o[(size_t)(r0g + 8) * D_ + c]) =
            __floats2half2_rn(oacc[ni][2] * inv1, oacc[ni][3] * inv1);
    }
}

// ---------------------------------------------------------------------------
// launch
// ---------------------------------------------------------------------------
extern "C" void kernel_launch(void* const* d_in, const int* in_sizes, int n_in,
                              void* d_out, int out_size)
{
    (void)in_sizes; (void)n_in; (void)out_size;
    const float* x     = (const float*)d_in[0];
    const float* W_in  = (const float*)d_in[1];
    const float* b_in  = (const float*)d_in[2];
    const float* W_out = (const float*)d_in[3];
    const float* b_out = (const float*)d_in[4];
    float* out = (float*)d_out;

    __half *xh, *wih, *woh, *qkvh, *oh;
    cudaGetSymbolAddress((void**)&xh,   g_xh);
    cudaGetSymbolAddress((void**)&wih,  g_wih);
    cudaGetSymbolAddress((void**)&woh,  g_woh);
    cudaGetSymbolAddress((void**)&qkvh, g_qkvh);
    cudaGetSymbolAddress((void**)&oh,   g_oh);

    cudaFuncSetAttribute(gemm_f16_kernel<true>,
                         cudaFuncAttributeMaxDynamicSharedMemorySize, 73728);
    cudaFuncSetAttribute(gemm_f16_kernel<false>,
                         cudaFuncAttributeMaxDynamicSharedMemorySize, 73728);

    // 0) convert inputs to fp16 scratch
    cvt_f16_kernel<<<512, 256>>>((const float4*)x,     (__half2*)xh,
                                 (B_ * S_ * D_) / 4);
    cvt_f16_kernel<<<256, 256>>>((const float4*)W_in,  (__half2*)wih,
                                 (3 * D_ * D_) / 4);
    cvt_f16_kernel<<<128, 256>>>((const float4*)W_out, (__half2*)woh,
                                 (D_ * D_) / 4);

    // 1) per-token QKV: [8192,1024] @ [3072,1024]^T + b_in  -> half
    dim3 g1(3072 / 128, 8192 / 128);
    gemm_f16_kernel<true><<<g1, 256, 73728>>>(xh, wih, b_in, qkvh,
                                              B_ * S_, 3 * D_, D_);

    // 2) windowed flash attention -> half
    const int nblk = B_ * NFULL * H_ * 16 + B_ * H_ * 8;  // 3840
    attn_kernel<<<nblk, 128, 46080>>>(qkvh, oh);

    // 3) output projection: [15360,1024] @ [1024,1024]^T + b_out -> fp32
    dim3 g3(1024 / 128, (B_ * ROWS_OUT) / 128);
    gemm_f16_kernel<false><<<g3, 256, 73728>>>(oh, woh, b_out, out,
                                               B_ * ROWS_OUT, D_, D_);
}